// round 4
// baseline (speedup 1.0000x reference)
#include <cuda_runtime.h>
#include <cuda_bf16.h>
#include <cstdint>

// ---------------------------------------------------------------------------
// Problem constants
// ---------------------------------------------------------------------------
#define NMODES   128
#define TWO_N    256
#define NLAYERS  8
#define BATCH    131072
#define M_TILE   64
#define NTILES   (BATCH / M_TILE)      // 2048
#define GRID_P   148
#define NTHREADS 512

#define S_C  0.70710678118654752440f

// ---------------------------------------------------------------------------
// Shared memory layout
// ---------------------------------------------------------------------------
#define OFF_WH   1024
#define OFF_WL   (OFF_WH + 65536)
#define OFF_A    (OFF_WL + 65536)              // 2 buffers x (Ah 16K + Al 16K)
#define SMEM_BYTES (OFF_A + 2 * 32768)         // 197632

// ---------------------------------------------------------------------------
// Global scratch
// ---------------------------------------------------------------------------
__device__ float          g_S[TWO_N * TWO_N];
__device__ float4         g_blk[NLAYERS * NMODES];
__device__ __nv_bfloat16  g_Wh[TWO_N * NMODES];
__device__ __nv_bfloat16  g_Wl[TWO_N * NMODES];
__device__ float          g_c[NMODES];

// ---------------------------------------------------------------------------
// Kernel 0: per-(layer,mode) local 2x2 blocks
// ---------------------------------------------------------------------------
__global__ __launch_bounds__(256) void blk_kernel(const float* __restrict__ params)
{
    int idx = blockIdx.x * 256 + threadIdx.x;
    int l = idx >> 7, b = idx & 127;
    float th1 = params[l * (3 * NMODES) + 3 * b + 0];
    float r   = params[l * (3 * NMODES) + 3 * b + 1];
    float th2 = params[l * (3 * NMODES) + 3 * b + 2];
    float s1, c1, s2, c2;
    sincosf(th1, &s1, &c1);
    sincosf(th2, &s2, &c2);
    float em = expf(-r), ep = expf(r);
    float A00 =  em * c1, A01 = -em * s1;
    float A10 =  ep * s1, A11 =  ep * c1;
    g_blk[idx] = make_float4(c2 * A00 - s2 * A10,
                             c2 * A01 - s2 * A11,
                             s2 * A00 + c2 * A10,
                             s2 * A01 + c2 * A11);
}

// ---------------------------------------------------------------------------
// Kernel 1: build S (one warp per column, beamsplitter chain = warp scan)
// ---------------------------------------------------------------------------
__device__ __forceinline__ void bs_chain(float t[4], int lane)
{
    const unsigned FULL = 0xffffffffu;
    float lv0 = (lane == 0) ? t[0] : S_C * t[0];
    float lv1 = S_C * (lv0 + t[1]);
    float lv2 = S_C * (lv1 + t[2]);
    float lv3 = S_C * (lv2 + t[3]);
    float carry = lv3;
    float o;
    o = __shfl_up_sync(FULL, carry, 1);  if (lane >= 1)  carry = fmaf(0.25f,                 o, carry);
    o = __shfl_up_sync(FULL, carry, 2);  if (lane >= 2)  carry = fmaf(0.0625f,               o, carry);
    o = __shfl_up_sync(FULL, carry, 4);  if (lane >= 4)  carry = fmaf(0.00390625f,           o, carry);
    o = __shfl_up_sync(FULL, carry, 8);  if (lane >= 8)  carry = fmaf(1.52587890625e-05f,    o, carry);
    o = __shfl_up_sync(FULL, carry, 16); if (lane >= 16) carry = fmaf(2.3283064365386963e-10f, o, carry);
    float exc = __shfl_up_sync(FULL, carry, 1);
    if (lane == 0) exc = 0.f;
    float u0 = fmaf(S_C,                  exc, lv0);
    float u1 = fmaf(0.5f,                 exc, lv1);
    float u2 = fmaf(0.35355339059327373f, exc, lv2);
    float u3 = fmaf(0.25f,                exc, lv3);
    float tn = __shfl_down_sync(FULL, t[0], 1);
    t[0] = S_C * (u0 - t[1]);
    t[1] = S_C * (u1 - t[2]);
    t[2] = S_C * (u2 - t[3]);
    t[3] = (lane == 31) ? u3 : S_C * (u3 - tn);
}

__global__ __launch_bounds__(256) void build_S_kernel()
{
    int c    = blockIdx.x * 8 + (threadIdx.x >> 5);
    int lane = threadIdx.x & 31;
    float x[4], p[4];
#pragma unroll
    for (int j = 0; j < 4; ++j) {
        int b = 4 * lane + j;
        x[j] = (c == 2 * b)     ? 1.f : 0.f;
        p[j] = (c == 2 * b + 1) ? 1.f : 0.f;
    }
    for (int l = 0; l < NLAYERS; ++l) {
#pragma unroll
        for (int j = 0; j < 4; ++j) {
            float4 Bv = g_blk[l * NMODES + 4 * lane + j];
            float nx = Bv.x * x[j] + Bv.y * p[j];
            float np = Bv.z * x[j] + Bv.w * p[j];
            x[j] = nx; p[j] = np;
        }
        bs_chain(x, lane);
        bs_chain(p, lane);
    }
#pragma unroll
    for (int j = 0; j < 4; ++j) {
        int b = 4 * lane + j;
        g_S[(2 * b)     * TWO_N + c] = x[j];
        g_S[(2 * b + 1) * TWO_N + c] = p[j];
    }
}

// ---------------------------------------------------------------------------
// Kernel 2: pack W (bf16 hi/lo) and per-mode constants
// ---------------------------------------------------------------------------
__global__ __launch_bounds__(128) void pack_kernel()
{
    int i = blockIdx.x;
    int t = threadIdx.x;
    const float* r0 = g_S + (2 * i)     * TWO_N;
    const float* r1 = g_S + (2 * i + 1) * TWO_N;
    float a0 = r0[t], a1 = r0[t + 128], b0 = r1[t], b1 = r1[t + 128];
    float sq = a0 * a0 + a1 * a1 + b0 * b0 + b1 * b1;
    __shared__ float red[128];
    red[t] = sq;
    __syncthreads();
    for (int off = 64; off > 0; off >>= 1) {
        if (t < off) red[t] += red[t + off];
        __syncthreads();
    }
    if (t == 0) g_c[i] = red[0] * 0.25f - 0.5f;

    float w0 = r0[2 * t];
    float w1 = r1[2 * t];
    __nv_bfloat16 h0 = __float2bfloat16(w0);
    __nv_bfloat16 h1 = __float2bfloat16(w1);
    g_Wh[(2 * i)     * NMODES + t] = h0;
    g_Wh[(2 * i + 1) * NMODES + t] = h1;
    g_Wl[(2 * i)     * NMODES + t] = __float2bfloat16(w0 - __bfloat162float(h0));
    g_Wl[(2 * i + 1) * NMODES + t] = __float2bfloat16(w1 - __bfloat162float(h1));
}

// ---------------------------------------------------------------------------
// Kernel 3: persistent HMMA GEMM, 512 threads, warp tile m16 x n64
// ---------------------------------------------------------------------------
__device__ __forceinline__ void ldsm_x4(unsigned addr, unsigned& r0, unsigned& r1,
                                        unsigned& r2, unsigned& r3)
{
    asm volatile("ldmatrix.sync.aligned.m8n8.x4.shared.b16 {%0,%1,%2,%3}, [%4];"
                 : "=r"(r0), "=r"(r1), "=r"(r2), "=r"(r3) : "r"(addr));
}
__device__ __forceinline__ void mma_bf16(float* d, const unsigned* a, const unsigned* b)
{
    asm volatile("mma.sync.aligned.m16n8k16.row.col.f32.bf16.bf16.f32 "
                 "{%0,%1,%2,%3}, {%4,%5,%6,%7}, {%8,%9}, {%0,%1,%2,%3};"
                 : "+f"(d[0]), "+f"(d[1]), "+f"(d[2]), "+f"(d[3])
                 : "r"(a[0]), "r"(a[1]), "r"(a[2]), "r"(a[3]), "r"(b[0]), "r"(b[1]));
}

__device__ __forceinline__ void load_A(float4 pf[4], const float* __restrict__ x,
                                       int tile, int tid)
{
    size_t m0 = (size_t)tile * M_TILE;
#pragma unroll
    for (int it = 0; it < 2; ++it) {
        int idx = tid + it * NTHREADS;
        int rr = idx >> 4, cc = idx & 15;
        const float4* g = (const float4*)(x + (m0 + rr) * NMODES + cc * 8);
        pf[2 * it]     = __ldg(g);
        pf[2 * it + 1] = __ldg(g + 1);
    }
}

__device__ __forceinline__ void convert_A(char* smem, unsigned aoff,
                                          const float4 pf[4], int tid)
{
#pragma unroll
    for (int it = 0; it < 2; ++it) {
        int idx = tid + it * NTHREADS;
        int rr = idx >> 4, cc = idx & 15;
        float vs[8] = {pf[2*it].x, pf[2*it].y, pf[2*it].z, pf[2*it].w,
                       pf[2*it+1].x, pf[2*it+1].y, pf[2*it+1].z, pf[2*it+1].w};
        union { __nv_bfloat16 b[8]; uint4 u4; } hh, ll;
#pragma unroll
        for (int k = 0; k < 8; ++k) {
            __nv_bfloat16 h = __float2bfloat16(vs[k]);
            hh.b[k] = h;
            ll.b[k] = __float2bfloat16(vs[k] - __bfloat162float(h));
        }
        unsigned off = rr * 256 + ((cc ^ (rr & 7)) << 4);
        *(uint4*)(smem + aoff + off)         = hh.u4;
        *(uint4*)(smem + aoff + 16384 + off) = ll.u4;
    }
}

__global__ __launch_bounds__(NTHREADS, 1) void gemm_kernel(const float* __restrict__ x,
                                                           float* __restrict__ out)
{
    extern __shared__ char smem[];
    const unsigned sbase = (unsigned)__cvta_generic_to_shared(smem);
    int tid = threadIdx.x, lane = tid & 31, wid = tid >> 5;
    int wm = wid & 3;          // 4 m-groups x 16 rows
    int wn = wid >> 2;         // 4 n-groups x 64 j-cols

    // ---- Stage W (hi+lo): 256 rows x 256B, swizzled ----
#pragma unroll
    for (int it = 0; it < 16; ++it) {
        int idx = tid + it * NTHREADS;               // 0..8191 units of 16B
        int arr = idx >> 12;
        int rr  = (idx >> 4) & 255;
        int cc  = idx & 15;
        uint4 v = *(const uint4*)((arr ? g_Wl : g_Wh) + rr * NMODES + cc * 8);
        *(uint4*)(smem + (arr ? OFF_WL : OFF_WH) + rr * 256 + ((cc ^ (rr & 7)) << 4)) = v;
    }

    // per-thread epilogue constants
    float cvals[8];
#pragma unroll
    for (int nt = 0; nt < 8; ++nt)
        cvals[nt] = __ldg(&g_c[wn * 32 + nt * 4 + (lane & 3)]);

    // ldsm lane mappings
    int a_row = (lane & 15);                 // + wm*16
    int a_cc  = (lane >> 4);                 // +2ks
    int b_row = ((lane >> 4) << 3) + (lane & 7);   // within 16-row pair block
    int b_cc  = ((lane >> 3) & 1);           // +2ks

    // ---- prologue ----
    int t = blockIdx.x;
    float4 pf[4];
    load_A(pf, x, t, tid);
    convert_A(smem, OFF_A, pf, tid);
    if (t + GRID_P < NTILES) load_A(pf, x, t + GRID_P, tid);
    __syncthreads();

    int buf = 0;
    while (t < NTILES) {
        // ---- MMA: 3 passes x 8 k-steps ----
        float acc[8][4];
#pragma unroll
        for (int nt = 0; nt < 8; ++nt)
#pragma unroll
            for (int q = 0; q < 4; ++q) acc[nt][q] = 0.f;

        unsigned Ah = sbase + OFF_A + buf * 32768;
#pragma unroll 1
        for (int pass = 0; pass < 3; ++pass) {
            unsigned Abase = (pass < 2) ? Ah : (Ah + 16384);
            unsigned Bbase = sbase + ((pass == 1) ? OFF_WL : OFF_WH);
#pragma unroll
            for (int ks = 0; ks < 8; ++ks) {
                unsigned afr[4];
                {
                    int ar = wm * 16 + a_row;
                    int cc = 2 * ks + a_cc;
                    unsigned addr = Abase + ar * 256 + ((cc ^ (ar & 7)) << 4);
                    ldsm_x4(addr, afr[0], afr[1], afr[2], afr[3]);
                }
#pragma unroll
                for (int p = 0; p < 4; ++p) {
                    int br = wn * 64 + p * 16 + b_row;
                    int cc = 2 * ks + b_cc;
                    unsigned addr = Bbase + br * 256 + ((cc ^ (br & 7)) << 4);
                    unsigned b0, b1, b2, b3;
                    ldsm_x4(addr, b0, b1, b2, b3);
                    unsigned bA[2] = {b0, b1}, bB[2] = {b2, b3};
                    mma_bf16(acc[2 * p],     afr, bA);
                    mma_bf16(acc[2 * p + 1], afr, bB);
                }
            }
        }

        // ---- convert next tile into other buffer (no barrier needed yet) ----
        if (t + GRID_P < NTILES)
            convert_A(smem, OFF_A + (buf ^ 1) * 32768, pf, tid);

        // ---- epilogue: direct stores (adjacent col pairs live in-thread) ----
        {
            size_t m0 = (size_t)t * M_TILE;
            float* o0 = out + (m0 + wm * 16 + (lane >> 2)) * NMODES
                            + wn * 32 + (lane & 3);
#pragma unroll
            for (int nt = 0; nt < 8; ++nt) {
                float* a = acc[nt];
                o0[nt * 4]               = fmaf(a[0], a[0], fmaf(a[1], a[1], cvals[nt]));
                o0[8 * NMODES + nt * 4]  = fmaf(a[2], a[2], fmaf(a[3], a[3], cvals[nt]));
            }
        }

        // ---- prefetch tile t+2*GRID_P ----
        if (t + 2 * GRID_P < NTILES) load_A(pf, x, t + 2 * GRID_P, tid);

        __syncthreads();
        t += GRID_P;
        buf ^= 1;
    }
}

// ---------------------------------------------------------------------------
// Launch
// ---------------------------------------------------------------------------
extern "C" void kernel_launch(void* const* d_in, const int* in_sizes, int n_in,
                              void* d_out, int out_size)
{
    const float* inputs = (const float*)d_in[0];
    const float* params = (const float*)d_in[1];
    float* out = (float*)d_out;

    cudaFuncSetAttribute(gemm_kernel, cudaFuncAttributeMaxDynamicSharedMemorySize,
                         SMEM_BYTES);

    blk_kernel<<<4, 256>>>(params);
    build_S_kernel<<<32, 256>>>();
    pack_kernel<<<NMODES, 128>>>();
    gemm_kernel<<<GRID_P, NTHREADS, SMEM_BYTES>>>(inputs, out);
}

// round 5
// speedup vs baseline: 1.0955x; 1.0955x over previous
#include <cuda_runtime.h>
#include <cuda_bf16.h>
#include <cstdint>

// ---------------------------------------------------------------------------
// Problem constants
// ---------------------------------------------------------------------------
#define NMODES   128
#define TWO_N    256
#define NLAYERS  8
#define BATCH    131072
#define M_TILE   128
#define NTILES   (BATCH / M_TILE)      // 1024
#define GRID_P   148
#define NTHREADS 512

#define S_C  0.70710678118654752440f

// ---------------------------------------------------------------------------
// Shared memory layout: W (hi+lo) 128K, A (hi+lo) 64K
// ---------------------------------------------------------------------------
#define OFF_WH   0
#define OFF_WL   65536
#define OFF_A    131072
#define SMEM_BYTES (OFF_A + 65536)     // 196608

// ---------------------------------------------------------------------------
// Global scratch
// ---------------------------------------------------------------------------
__device__ float          g_S[TWO_N * TWO_N];
__device__ float4         g_blk[NLAYERS * NMODES];
__device__ __nv_bfloat16  g_Wh[TWO_N * NMODES];
__device__ __nv_bfloat16  g_Wl[TWO_N * NMODES];
__device__ float          g_c[NMODES];

// ---------------------------------------------------------------------------
// Kernel 0: per-(layer,mode) local 2x2 blocks
// ---------------------------------------------------------------------------
__global__ __launch_bounds__(256) void blk_kernel(const float* __restrict__ params)
{
    int idx = blockIdx.x * 256 + threadIdx.x;
    int l = idx >> 7, b = idx & 127;
    float th1 = params[l * (3 * NMODES) + 3 * b + 0];
    float r   = params[l * (3 * NMODES) + 3 * b + 1];
    float th2 = params[l * (3 * NMODES) + 3 * b + 2];
    float s1, c1, s2, c2;
    sincosf(th1, &s1, &c1);
    sincosf(th2, &s2, &c2);
    float em = expf(-r), ep = expf(r);
    float A00 =  em * c1, A01 = -em * s1;
    float A10 =  ep * s1, A11 =  ep * c1;
    g_blk[idx] = make_float4(c2 * A00 - s2 * A10,
                             c2 * A01 - s2 * A11,
                             s2 * A00 + c2 * A10,
                             s2 * A01 + c2 * A11);
}

// ---------------------------------------------------------------------------
// Kernel 1: build S (one warp per column, beamsplitter chain = warp scan)
// ---------------------------------------------------------------------------
__device__ __forceinline__ void bs_chain(float t[4], int lane)
{
    const unsigned FULL = 0xffffffffu;
    float lv0 = (lane == 0) ? t[0] : S_C * t[0];
    float lv1 = S_C * (lv0 + t[1]);
    float lv2 = S_C * (lv1 + t[2]);
    float lv3 = S_C * (lv2 + t[3]);
    float carry = lv3;
    float o;
    o = __shfl_up_sync(FULL, carry, 1);  if (lane >= 1)  carry = fmaf(0.25f,                 o, carry);
    o = __shfl_up_sync(FULL, carry, 2);  if (lane >= 2)  carry = fmaf(0.0625f,               o, carry);
    o = __shfl_up_sync(FULL, carry, 4);  if (lane >= 4)  carry = fmaf(0.00390625f,           o, carry);
    o = __shfl_up_sync(FULL, carry, 8);  if (lane >= 8)  carry = fmaf(1.52587890625e-05f,    o, carry);
    o = __shfl_up_sync(FULL, carry, 16); if (lane >= 16) carry = fmaf(2.3283064365386963e-10f, o, carry);
    float exc = __shfl_up_sync(FULL, carry, 1);
    if (lane == 0) exc = 0.f;
    float u0 = fmaf(S_C,                  exc, lv0);
    float u1 = fmaf(0.5f,                 exc, lv1);
    float u2 = fmaf(0.35355339059327373f, exc, lv2);
    float u3 = fmaf(0.25f,                exc, lv3);
    float tn = __shfl_down_sync(FULL, t[0], 1);
    t[0] = S_C * (u0 - t[1]);
    t[1] = S_C * (u1 - t[2]);
    t[2] = S_C * (u2 - t[3]);
    t[3] = (lane == 31) ? u3 : S_C * (u3 - tn);
}

__global__ __launch_bounds__(256) void build_S_kernel()
{
    int c    = blockIdx.x * 8 + (threadIdx.x >> 5);
    int lane = threadIdx.x & 31;
    float x[4], p[4];
#pragma unroll
    for (int j = 0; j < 4; ++j) {
        int b = 4 * lane + j;
        x[j] = (c == 2 * b)     ? 1.f : 0.f;
        p[j] = (c == 2 * b + 1) ? 1.f : 0.f;
    }
    for (int l = 0; l < NLAYERS; ++l) {
#pragma unroll
        for (int j = 0; j < 4; ++j) {
            float4 Bv = g_blk[l * NMODES + 4 * lane + j];
            float nx = Bv.x * x[j] + Bv.y * p[j];
            float np = Bv.z * x[j] + Bv.w * p[j];
            x[j] = nx; p[j] = np;
        }
        bs_chain(x, lane);
        bs_chain(p, lane);
    }
#pragma unroll
    for (int j = 0; j < 4; ++j) {
        int b = 4 * lane + j;
        g_S[(2 * b)     * TWO_N + c] = x[j];
        g_S[(2 * b + 1) * TWO_N + c] = p[j];
    }
}

// ---------------------------------------------------------------------------
// Kernel 2: pack W (bf16 hi/lo) and per-mode constants
// ---------------------------------------------------------------------------
__global__ __launch_bounds__(128) void pack_kernel()
{
    int i = blockIdx.x;
    int t = threadIdx.x;
    const float* r0 = g_S + (2 * i)     * TWO_N;
    const float* r1 = g_S + (2 * i + 1) * TWO_N;
    float a0 = r0[t], a1 = r0[t + 128], b0 = r1[t], b1 = r1[t + 128];
    float sq = a0 * a0 + a1 * a1 + b0 * b0 + b1 * b1;
    __shared__ float red[128];
    red[t] = sq;
    __syncthreads();
    for (int off = 64; off > 0; off >>= 1) {
        if (t < off) red[t] += red[t + off];
        __syncthreads();
    }
    if (t == 0) g_c[i] = red[0] * 0.25f - 0.5f;

    float w0 = r0[2 * t];
    float w1 = r1[2 * t];
    __nv_bfloat16 h0 = __float2bfloat16(w0);
    __nv_bfloat16 h1 = __float2bfloat16(w1);
    g_Wh[(2 * i)     * NMODES + t] = h0;
    g_Wh[(2 * i + 1) * NMODES + t] = h1;
    g_Wl[(2 * i)     * NMODES + t] = __float2bfloat16(w0 - __bfloat162float(h0));
    g_Wl[(2 * i + 1) * NMODES + t] = __float2bfloat16(w1 - __bfloat162float(h1));
}

// ---------------------------------------------------------------------------
// Kernel 3: persistent HMMA GEMM, 512 threads, warp tile m32 x n64.
// W rows are permuted in smem so each thread's D columns map to contiguous
// output modes -> dense STG.128 epilogue straight from registers.
//
// smem B row position r: wn = r>>6, p = r&63, nt = p>>3, c = (p>>1)&3,
// par = p&1, mode_local = c*4 + (nt&3) + (nt>>2)*16,
// source W row j = wn*64 + 2*mode_local + par.
// ---------------------------------------------------------------------------
__device__ __forceinline__ void ldsm_x4(unsigned addr, unsigned& r0, unsigned& r1,
                                        unsigned& r2, unsigned& r3)
{
    asm volatile("ldmatrix.sync.aligned.m8n8.x4.shared.b16 {%0,%1,%2,%3}, [%4];"
                 : "=r"(r0), "=r"(r1), "=r"(r2), "=r"(r3) : "r"(addr));
}
__device__ __forceinline__ void mma_bf16(float* d, const unsigned* a, const unsigned* b)
{
    asm volatile("mma.sync.aligned.m16n8k16.row.col.f32.bf16.bf16.f32 "
                 "{%0,%1,%2,%3}, {%4,%5,%6,%7}, {%8,%9}, {%0,%1,%2,%3};"
                 : "+f"(d[0]), "+f"(d[1]), "+f"(d[2]), "+f"(d[3])
                 : "r"(a[0]), "r"(a[1]), "r"(a[2]), "r"(a[3]), "r"(b[0]), "r"(b[1]));
}

__device__ __forceinline__ void load_A(float4 pf[8], const float* __restrict__ x,
                                       int tile, int tid)
{
    size_t m0 = (size_t)tile * M_TILE;
#pragma unroll
    for (int it = 0; it < 4; ++it) {
        int idx = tid + it * NTHREADS;          // 0..2047 chunks of 8 floats
        int rr = idx >> 4, cc = idx & 15;
        const float4* g = (const float4*)(x + (m0 + rr) * NMODES + cc * 8);
        pf[2 * it]     = __ldg(g);
        pf[2 * it + 1] = __ldg(g + 1);
    }
}

__device__ __forceinline__ void convert_A(char* smem, const float4 pf[8], int tid)
{
#pragma unroll
    for (int it = 0; it < 4; ++it) {
        int idx = tid + it * NTHREADS;
        int rr = idx >> 4, cc = idx & 15;
        float vs[8] = {pf[2*it].x, pf[2*it].y, pf[2*it].z, pf[2*it].w,
                       pf[2*it+1].x, pf[2*it+1].y, pf[2*it+1].z, pf[2*it+1].w};
        union { __nv_bfloat16 b[8]; uint4 u4; } hh, ll;
#pragma unroll
        for (int k = 0; k < 8; ++k) {
            __nv_bfloat16 h = __float2bfloat16(vs[k]);
            hh.b[k] = h;
            ll.b[k] = __float2bfloat16(vs[k] - __bfloat162float(h));
        }
        unsigned off = rr * 256 + ((cc ^ (rr & 7)) << 4);
        *(uint4*)(smem + OFF_A + off)         = hh.u4;
        *(uint4*)(smem + OFF_A + 32768 + off) = ll.u4;
    }
}

__global__ __launch_bounds__(NTHREADS, 1) void gemm_kernel(const float* __restrict__ x,
                                                           float* __restrict__ out)
{
    extern __shared__ char smem[];
    const unsigned sbase = (unsigned)__cvta_generic_to_shared(smem);
    int tid = threadIdx.x, lane = tid & 31, wid = tid >> 5;
    int wm = wid & 3;          // 4 m-groups x 32 rows
    int wn = wid >> 2;         // 4 n-groups x 64 y-cols (32 modes)

    // ---- Stage W (hi+lo) with N-permutation, swizzled 256B rows ----
#pragma unroll
    for (int it = 0; it < 16; ++it) {
        int idx = tid + it * NTHREADS;               // 0..8191 units of 16B
        int arr = idx >> 12;
        int rr  = (idx >> 4) & 255;                  // smem row
        int cc  = idx & 15;
        int p   = rr & 63;
        int nt  = p >> 3, c = (p >> 1) & 3, par = p & 1;
        int ml  = c * 4 + (nt & 3) + ((nt >> 2) << 4);
        int j   = (rr & ~63) + 2 * ml + par;         // source W row
        uint4 v = *(const uint4*)((arr ? g_Wl : g_Wh) + j * NMODES + cc * 8);
        *(uint4*)(smem + (arr ? OFF_WL : OFF_WH) + rr * 256 + ((cc ^ (rr & 7)) << 4)) = v;
    }

    // per-thread epilogue constants: modes wn*32 + (lane&3)*4 + (nt&3) + (nt>>2)*16
    float cvals[8];
#pragma unroll
    for (int nt = 0; nt < 8; ++nt)
        cvals[nt] = __ldg(&g_c[wn * 32 + (lane & 3) * 4 + (nt & 3) + ((nt >> 2) << 4)]);

    // ldsm lane mappings
    int a_row = (lane & 15);
    int a_cc  = (lane >> 4);
    int b_row = ((lane >> 4) << 3) + (lane & 7);
    int b_cc  = ((lane >> 3) & 1);

    // ---- prologue ----
    int t = blockIdx.x;
    float4 pf[8];
    load_A(pf, x, t, tid);
    convert_A(smem, pf, tid);
    if (t + GRID_P < NTILES) load_A(pf, x, t + GRID_P, tid);
    __syncthreads();

    while (t < NTILES) {
        // ---- MMA: 3 passes x 8 k-steps, warp tile m32 x n64 ----
        float acc[2][8][4];
#pragma unroll
        for (int mf = 0; mf < 2; ++mf)
#pragma unroll
            for (int nt = 0; nt < 8; ++nt)
#pragma unroll
                for (int q = 0; q < 4; ++q) acc[mf][nt][q] = 0.f;

#pragma unroll 1
        for (int pass = 0; pass < 3; ++pass) {
            unsigned Abase = sbase + OFF_A + (pass == 2 ? 32768 : 0);
            unsigned Bbase = sbase + ((pass == 1) ? OFF_WL : OFF_WH);
#pragma unroll
            for (int ks = 0; ks < 8; ++ks) {
                unsigned afr[2][4];
#pragma unroll
                for (int mf = 0; mf < 2; ++mf) {
                    int ar = wm * 32 + mf * 16 + a_row;
                    int cc = 2 * ks + a_cc;
                    unsigned addr = Abase + ar * 256 + ((cc ^ (ar & 7)) << 4);
                    ldsm_x4(addr, afr[mf][0], afr[mf][1], afr[mf][2], afr[mf][3]);
                }
#pragma unroll
                for (int p = 0; p < 4; ++p) {
                    int br = wn * 64 + p * 16 + b_row;
                    int cc = 2 * ks + b_cc;
                    unsigned addr = Bbase + br * 256 + ((cc ^ (br & 7)) << 4);
                    unsigned b0, b1, b2, b3;
                    ldsm_x4(addr, b0, b1, b2, b3);
                    unsigned bA[2] = {b0, b1}, bB[2] = {b2, b3};
                    mma_bf16(acc[0][2 * p],     afr[0], bA);
                    mma_bf16(acc[1][2 * p],     afr[1], bA);
                    mma_bf16(acc[0][2 * p + 1], afr[0], bB);
                    mma_bf16(acc[1][2 * p + 1], afr[1], bB);
                }
            }
        }
        __syncthreads();                     // all A-smem reads done

        // ---- convert next tile + prefetch tile after ----
        bool have_next = (t + GRID_P < NTILES);
        if (have_next) {
            convert_A(smem, pf, tid);
            if (t + 2 * GRID_P < NTILES) load_A(pf, x, t + 2 * GRID_P, tid);
        }

        // ---- epilogue: dense STG.128 from registers ----
        {
            size_t m0 = (size_t)t * M_TILE;
            int mode0 = wn * 32 + (lane & 3) * 4;
#pragma unroll
            for (int mf = 0; mf < 2; ++mf) {
#pragma unroll
                for (int h = 0; h < 2; ++h) {
                    int row = wm * 32 + mf * 16 + (lane >> 2) + h * 8;
                    float* o = out + (m0 + row) * NMODES + mode0;
                    float v[8];
#pragma unroll
                    for (int nt = 0; nt < 8; ++nt) {
                        float f0 = acc[mf][nt][2 * h];
                        float f1 = acc[mf][nt][2 * h + 1];
                        v[nt] = fmaf(f0, f0, fmaf(f1, f1, cvals[nt]));
                    }
                    *(float4*)(o)      = make_float4(v[0], v[1], v[2], v[3]);
                    *(float4*)(o + 16) = make_float4(v[4], v[5], v[6], v[7]);
                }
            }
        }

        __syncthreads();                     // A smem ready for next MMA
        t += GRID_P;
    }
}

// ---------------------------------------------------------------------------
// Launch
// ---------------------------------------------------------------------------
extern "C" void kernel_launch(void* const* d_in, const int* in_sizes, int n_in,
                              void* d_out, int out_size)
{
    const float* inputs = (const float*)d_in[0];
    const float* params = (const float*)d_in[1];
    float* out = (float*)d_out;

    cudaFuncSetAttribute(gemm_kernel, cudaFuncAttributeMaxDynamicSharedMemorySize,
                         SMEM_BYTES);

    blk_kernel<<<4, 256>>>(params);
    build_S_kernel<<<32, 256>>>();
    pack_kernel<<<NMODES, 128>>>();
    gemm_kernel<<<GRID_P, NTHREADS, SMEM_BYTES>>>(inputs, out);
}